// round 11
// baseline (speedup 1.0000x reference)
#include <cuda_runtime.h>
#include <cuda_bf16.h>
#include <math.h>
#include <stdint.h>

// ---------------------------------------------------------------------------
// Problem constants
// ---------------------------------------------------------------------------
#define BATCH   8192
#define IN_DIM  4096
#define OUT_DIM 2048
#define DEPTH   9
#define RSTEPS  27
#define WIN     55
#define CENTER  27

// GEMM tiling: 64x64 CTA tile, 128 threads, 3 CTAs/SM, 4-stage ring
#define BM 64
#define BN 64
#define BK 32
#define NKT (IN_DIM / BK)            // 128
#define STAGES 4
// Stage layout: Ahi 4K | Alo 4K | Bhi 4K | Blo 4K
#define AHI 0
#define ALO 4096
#define BHI 8192
#define BLO 12288
#define STAGE_BYTES 16384
#define SMEM_TOTAL (STAGES * STAGE_BYTES)   // 65536/CTA -> 3 CTAs = 192KB/SM

// ---------------------------------------------------------------------------
// Device-global scratch (static: no runtime allocation)
// ---------------------------------------------------------------------------
__device__ float         g_pb[OUT_DIM];
__device__ __nv_bfloat16 g_xhi[(size_t)BATCH * IN_DIM];
__device__ __nv_bfloat16 g_xlo[(size_t)BATCH * IN_DIM];
__device__ __nv_bfloat16 g_wThi[(size_t)OUT_DIM * IN_DIM];   // W^T [N][K]
__device__ __nv_bfloat16 g_wTlo[(size_t)OUT_DIM * IN_DIM];

// ---------------------------------------------------------------------------
// PTX helpers (base sm_103 ISA only: cp.async / ldmatrix / mma.sync)
// ---------------------------------------------------------------------------
__device__ __forceinline__ uint32_t smem_u32(const void* p) {
    uint32_t a;
    asm("{ .reg .u64 t; cvta.to.shared.u64 t, %1; cvt.u32.u64 %0, t; }"
        : "=r"(a) : "l"(p));
    return a;
}
__device__ __forceinline__ void cpasync16(uint32_t dst, const void* src) {
    asm volatile("cp.async.cg.shared.global [%0], [%1], 16;"
                 :: "r"(dst), "l"(src));
}
#define CP_COMMIT() asm volatile("cp.async.commit_group;" ::: "memory")
#define CP_WAIT1()  asm volatile("cp.async.wait_group 1;"  ::: "memory")
#define CP_WAIT2()  asm volatile("cp.async.wait_group 2;"  ::: "memory")

#define LDSM_X4(d, a) \
    asm volatile("ldmatrix.sync.aligned.m8n8.x4.shared.b16 {%0,%1,%2,%3}, [%4];" \
        : "=r"((d)[0]), "=r"((d)[1]), "=r"((d)[2]), "=r"((d)[3]) : "r"(a))

#define MMA16816(c, a, b) \
    asm volatile("mma.sync.aligned.m16n8k16.row.col.f32.bf16.bf16.f32 " \
        "{%0,%1,%2,%3}, {%4,%5,%6,%7}, {%8,%9}, {%0,%1,%2,%3};" \
        : "+f"((c)[0]), "+f"((c)[1]), "+f"((c)[2]), "+f"((c)[3]) \
        : "r"((a)[0]), "r"((a)[1]), "r"((a)[2]), "r"((a)[3]), \
          "r"((b)[0]), "r"((b)[1]))

// Swizzled smem offset for logical (row, 16B-chunk cc 0..3) of a 64B-row tile.
__device__ __forceinline__ uint32_t swz(uint32_t base, int row, int cc) {
    int p  = row >> 1;
    int c8 = ((row & 1) << 2) | cc;
    return base + p * 128 + ((c8 ^ (p & 7)) << 4);
}

// ---------------------------------------------------------------------------
// Kernel 1: universal probs (dependency-cone trick) + bias -> g_pb
// ---------------------------------------------------------------------------
__global__ void probs_kernel(const float* __restrict__ uw,
                             const float* __restrict__ bias) {
    int o = blockIdx.x * blockDim.x + threadIdx.x;
    if (o >= OUT_DIM) return;
    float w[WIN];
#pragma unroll
    for (int j = 0; j < WIN; j++) w[j] = 0.015625f;   // 1/sqrt(4096)
#pragma unroll
    for (int t = 0; t < RSTEPS; t++) {
        const int d = t / 3, g = t % 3;
        float ang = uw[(size_t)d * IN_DIM * OUT_DIM + (size_t)o * OUT_DIM + g];
        float s, c;
        sincosf(ang, &s, &c);
        float nw[WIN];
        nw[0] = w[0]; nw[WIN - 1] = w[WIN - 1];
#pragma unroll
        for (int j = 1; j < WIN - 1; j++)
            nw[j] = c * w[j] - s * w[j + 1] + s * w[j - 1];
#pragma unroll
        for (int j = 0; j < WIN; j++) w[j] = nw[j];
    }
    g_pb[o] = w[CENTER] * w[CENTER] + bias[o];
}

// ---------------------------------------------------------------------------
// Kernel 2: split x -> (hi, lo) bf16
// ---------------------------------------------------------------------------
__global__ void split_x_kernel(const float* __restrict__ x) {
    size_t i = ((size_t)blockIdx.x * blockDim.x + threadIdx.x) * 4;
    float4 v = *(const float4*)(x + i);
    __nv_bfloat16 h0 = __float2bfloat16(v.x);
    __nv_bfloat16 h1 = __float2bfloat16(v.y);
    __nv_bfloat16 h2 = __float2bfloat16(v.z);
    __nv_bfloat16 h3 = __float2bfloat16(v.w);
    __nv_bfloat162* ph = (__nv_bfloat162*)(g_xhi + i);
    __nv_bfloat162* pl = (__nv_bfloat162*)(g_xlo + i);
    ph[0] = __nv_bfloat162(h0, h1);
    ph[1] = __nv_bfloat162(h2, h3);
    pl[0] = __nv_bfloat162(__float2bfloat16(v.x - __bfloat162float(h0)),
                           __float2bfloat16(v.y - __bfloat162float(h1)));
    pl[1] = __nv_bfloat162(__float2bfloat16(v.z - __bfloat162float(h2)),
                           __float2bfloat16(v.w - __bfloat162float(h3)));
}

// ---------------------------------------------------------------------------
// Kernel 3: transpose + split W[k][n] -> wT_hi/lo[n][k]
// ---------------------------------------------------------------------------
__global__ void split_w_kernel(const float* __restrict__ W) {
    __shared__ float t[32][33];
    const int n0 = blockIdx.x * 32, k0 = blockIdx.y * 32;
    const int tx = threadIdx.x, ty = threadIdx.y;   // 32 x 8
#pragma unroll
    for (int i = 0; i < 32; i += 8)
        t[ty + i][tx] = W[(size_t)(k0 + ty + i) * OUT_DIM + n0 + tx];
    __syncthreads();
#pragma unroll
    for (int i = 0; i < 32; i += 8) {
        float v = t[tx][ty + i];
        __nv_bfloat16 h = __float2bfloat16(v);
        size_t o = (size_t)(n0 + ty + i) * IN_DIM + k0 + tx;
        g_wThi[o] = h;
        g_wTlo[o] = __float2bfloat16(v - __bfloat162float(h));
    }
}

// ---------------------------------------------------------------------------
// Kernel 4: C = tanh(x @ W + g_pb) via bf16x3 mma.sync GEMM.
// 64x64x32 CTA tile, 4 warps (2x2), warp tile 32x32, 4-stage ring,
// 3 CTAs/SM = 3 independent barrier domains (vs R9's 2): when one CTA's
// warps drain at a barrier, the other two CTAs keep the SMSP tensor units
// fed. Pipeline discipline is R9's proven pattern VERBATIM:
//   wait_group 1 + __syncthreads at loop top (wait->barrier->read),
//   one commit per chunk, refill slot (kt+3)&3 mid-iteration,
//   fragment double-buffering with B-x4 ldmatrix ni-pairs.
// ---------------------------------------------------------------------------
__global__ __launch_bounds__(128, 3)
void gemm_bf16x3_kernel(float* __restrict__ out) {
    extern __shared__ char smem[];
    const uint32_t sb = smem_u32(smem);

    const int tid  = threadIdx.x;
    const int lane = tid & 31;
    const int wid  = tid >> 5;
    const int wm   = wid >> 1;          // 0..1  -> m offset wm*32
    const int wn   = wid & 1;           // 0..1  -> n offset wn*32
    const int gid  = lane >> 2;
    const int tg   = lane & 3;
    const int bm   = blockIdx.y * BM;
    const int bn   = blockIdx.x * BN;

    // --- global load mapping: 8 x 16B chunks per thread per stage ---
    const int rr = tid >> 2;            // rows 0..31
    const int cc = tid & 3;             // 16B chunk in 64B row

    const __nv_bfloat16* pAh0 = g_xhi  + (size_t)(bm + rr)      * IN_DIM + cc * 8;
    const __nv_bfloat16* pAh1 = g_xhi  + (size_t)(bm + rr + 32) * IN_DIM + cc * 8;
    const __nv_bfloat16* pAl0 = g_xlo  + (size_t)(bm + rr)      * IN_DIM + cc * 8;
    const __nv_bfloat16* pAl1 = g_xlo  + (size_t)(bm + rr + 32) * IN_DIM + cc * 8;
    const __nv_bfloat16* pBh0 = g_wThi + (size_t)(bn + rr)      * IN_DIM + cc * 8;
    const __nv_bfloat16* pBh1 = g_wThi + (size_t)(bn + rr + 32) * IN_DIM + cc * 8;
    const __nv_bfloat16* pBl0 = g_wTlo + (size_t)(bn + rr)      * IN_DIM + cc * 8;
    const __nv_bfloat16* pBl1 = g_wTlo + (size_t)(bn + rr + 32) * IN_DIM + cc * 8;

    const uint32_t dAh0 = swz(AHI, rr,      cc);
    const uint32_t dAh1 = swz(AHI, rr + 32, cc);
    const uint32_t dAl0 = swz(ALO, rr,      cc);
    const uint32_t dAl1 = swz(ALO, rr + 32, cc);
    const uint32_t dBh0 = swz(BHI, rr,      cc);
    const uint32_t dBh1 = swz(BHI, rr + 32, cc);
    const uint32_t dBl0 = swz(BLO, rr,      cc);
    const uint32_t dBl1 = swz(BLO, rr + 32, cc);

    int kload = 0;
#define ISSUE_STAGE(stg)                                                     \
    do {                                                                     \
        uint32_t s_ = sb + (stg) * STAGE_BYTES;                              \
        cpasync16(s_ + dAh0, pAh0 + kload);                                  \
        cpasync16(s_ + dAh1, pAh1 + kload);                                  \
        cpasync16(s_ + dAl0, pAl0 + kload);                                  \
        cpasync16(s_ + dAl1, pAl1 + kload);                                  \
        cpasync16(s_ + dBh0, pBh0 + kload);                                  \
        cpasync16(s_ + dBh1, pBh1 + kload);                                  \
        cpasync16(s_ + dBl0, pBl0 + kload);                                  \
        cpasync16(s_ + dBl1, pBl1 + kload);                                  \
        kload += BK;                                                         \
    } while (0)

    // Prologue: fill stages 0..2 (stage 3 filled by iteration kt=0)
    ISSUE_STAGE(0); CP_COMMIT();
    ISSUE_STAGE(1); CP_COMMIT();
    ISSUE_STAGE(2); CP_COMMIT();

    float acc[2][4][4];
#pragma unroll
    for (int i = 0; i < 2; i++)
#pragma unroll
        for (int j = 0; j < 4; j++)
#pragma unroll
            for (int q = 0; q < 4; q++) acc[i][j][q] = 0.0f;

    // Per-lane ldmatrix logical coordinates
    const int a_rl = lane & 15;               // A: rows m0..m0+15
    const int a_ch = lane >> 4;               // A: +0 / +1 chunk
    // B x4 ni-pair mapping
    const int b4_row = ((lane >> 4) << 3) + (lane & 7);
    const int b4_c   = (lane >> 3) & 1;

    uint32_t oA[2][2], oB[2][2];              // oB: [ks][nj], nj = ni-pair
#pragma unroll
    for (int ks = 0; ks < 2; ks++) {
        const int ccA = ks * 2 + a_ch;
        const int ccB = ks * 2 + b4_c;
#pragma unroll
        for (int mi = 0; mi < 2; mi++)
            oA[ks][mi] = swz(0, wm * 32 + mi * 16 + a_rl, ccA);
#pragma unroll
        for (int nj = 0; nj < 2; nj++)
            oB[ks][nj] = swz(0, wn * 32 + nj * 16 + b4_row, ccB);
    }

    // Fragment registers: hi double-buffered, lo just-in-time
    uint32_t ah0[2][4], ah1[2][4];
    uint32_t bh0[4][2], bh1[4][2];
    uint32_t al[2][4],  bl[4][2];

#define LOAD_HI(AH, BH, SBASE, KS)                                           \
    do {                                                                     \
        LDSM_X4(AH[0],     (SBASE) + AHI + oA[KS][0]);                       \
        LDSM_X4(AH[1],     (SBASE) + AHI + oA[KS][1]);                       \
        LDSM_X4(&BH[0][0], (SBASE) + BHI + oB[KS][0]);                       \
        LDSM_X4(&BH[2][0], (SBASE) + BHI + oB[KS][1]);                       \
    } while (0)

#define LOAD_LO(SBASE, KS)                                                   \
    do {                                                                     \
        LDSM_X4(al[0],     (SBASE) + ALO + oA[KS][0]);                       \
        LDSM_X4(al[1],     (SBASE) + ALO + oA[KS][1]);                       \
        LDSM_X4(&bl[0][0], (SBASE) + BLO + oB[KS][0]);                       \
        LDSM_X4(&bl[2][0], (SBASE) + BLO + oB[KS][1]);                       \
    } while (0)

    // hh first (hi preloaded a phase ago), then hl / lh (lo just loaded,
    // its LDSM latency covered by the 8 hh MMAs).
#define MMA_PHASE(AH, BH)                                                    \
    do {                                                                     \
        _Pragma("unroll")                                                    \
        for (int mi = 0; mi < 2; mi++)                                       \
            _Pragma("unroll")                                                \
            for (int ni = 0; ni < 4; ni++)                                   \
                MMA16816(acc[mi][ni], AH[mi], BH[ni]);                       \
        _Pragma("unroll")                                                    \
        for (int mi = 0; mi < 2; mi++)                                       \
            _Pragma("unroll")                                                \
            for (int ni = 0; ni < 4; ni++)                                   \
                MMA16816(acc[mi][ni], AH[mi], bl[ni]);                       \
        _Pragma("unroll")                                                    \
        for (int mi = 0; mi < 2; mi++)                                       \
            _Pragma("unroll")                                                \
            for (int ni = 0; ni < 4; ni++)                                   \
                MMA16816(acc[mi][ni], al[mi], BH[ni]);                       \
    } while (0)

    // Prologue fragment load: g0 complete (wait2 with 3 commits), barrier,
    // then read stage 0. (wait -> barrier -> read, always.)
    CP_WAIT2();
    __syncthreads();
    LOAD_HI(ah0, bh0, sb + 0 * STAGE_BYTES, 0);

#pragma unroll 1
    for (int kt = 0; kt < NKT; kt++) {
        // wait_group 1: groups up to g_{kt+1} complete -> stages kt&3 and
        // (kt+1)&3 readable AFTER the barrier (cross-thread visibility).
        CP_WAIT1();
        __syncthreads();

        const uint32_t s_cur = sb + (kt & 3) * STAGE_BYTES;
        const uint32_t s_nxt = sb + ((kt + 1) & 3) * STAGE_BYTES;

        // ---- phase ks=0: consume (ah0,bh0), prefetch ks=1 hi ----
        LOAD_LO(s_cur, 0);
        LOAD_HI(ah1, bh1, s_cur, 1);
        MMA_PHASE(ah0, bh0);

        // Refill slot (kt+3)&3 = (kt-1)&3 (consumed at iter kt-1; the top
        // barrier of THIS iteration protects it). Mid-iteration placement
        // keeps the LSU burst off the barrier-exit critical path.
        if (kt + 3 < NKT) {
            ISSUE_STAGE((kt + 3) & 3);
        }
        CP_COMMIT();

        // ---- phase ks=1: consume (ah1,bh1), prefetch next chunk ks=0 hi ----
        LOAD_LO(s_cur, 1);
        LOAD_HI(ah0, bh0, s_nxt, 0);    // stale read at kt=NKT-1: never consumed
        MMA_PHASE(ah1, bh1);
    }

    // ------------------- epilogue: +pb, tanh, store -------------------
    float pbv[4][2];
#pragma unroll
    for (int ni = 0; ni < 4; ni++) {
        const int col = bn + wn * 32 + ni * 8 + tg * 2;
        pbv[ni][0] = g_pb[col];
        pbv[ni][1] = g_pb[col + 1];
    }
#pragma unroll
    for (int mi = 0; mi < 2; mi++) {
        const int r0 = bm + wm * 32 + mi * 16 + gid;
#pragma unroll
        for (int ni = 0; ni < 4; ni++) {
            const int col = bn + wn * 32 + ni * 8 + tg * 2;
            float2 v0, v1;
            v0.x = tanhf(acc[mi][ni][0] + pbv[ni][0]);
            v0.y = tanhf(acc[mi][ni][1] + pbv[ni][1]);
            v1.x = tanhf(acc[mi][ni][2] + pbv[ni][0]);
            v1.y = tanhf(acc[mi][ni][3] + pbv[ni][1]);
            *(float2*)(out + (size_t)r0 * OUT_DIM + col)       = v0;
            *(float2*)(out + (size_t)(r0 + 8) * OUT_DIM + col) = v1;
        }
    }
}

// ---------------------------------------------------------------------------
// Host launch
// ---------------------------------------------------------------------------
extern "C" void kernel_launch(void* const* d_in, const int* in_sizes, int n_in,
                              void* d_out, int out_size) {
    const float *x = nullptr, *uw = nullptr, *cw = nullptr, *cb = nullptr;
    for (int i = 0; i < n_in; i++) {
        switch (in_sizes[i]) {
            case BATCH * IN_DIM:           x  = (const float*)d_in[i]; break;
            case DEPTH * IN_DIM * OUT_DIM: uw = (const float*)d_in[i]; break;
            case IN_DIM * OUT_DIM:         cw = (const float*)d_in[i]; break;
            case OUT_DIM:                  cb = (const float*)d_in[i]; break;
            default: break;
        }
    }
    float* out = (float*)d_out;

    probs_kernel<<<OUT_DIM / 256, 256>>>(uw, cb);
    split_x_kernel<<<(BATCH * IN_DIM) / (4 * 256), 256>>>(x);
    split_w_kernel<<<dim3(OUT_DIM / 32, IN_DIM / 32), dim3(32, 8)>>>(cw);

    static int attr_done = 0;
    if (!attr_done) {
        cudaFuncSetAttribute(gemm_bf16x3_kernel,
                             cudaFuncAttributeMaxDynamicSharedMemorySize,
                             SMEM_TOTAL);
        attr_done = 1;
    }
    dim3 grid(OUT_DIM / BN, BATCH / BM);   // (32, 128)
    gemm_bf16x3_kernel<<<grid, 128, SMEM_TOTAL>>>(out);
}

// round 12
// speedup vs baseline: 1.0100x; 1.0100x over previous
#include <cuda_runtime.h>
#include <cuda_bf16.h>
#include <math.h>
#include <stdint.h>

// ---------------------------------------------------------------------------
// Problem constants
// ---------------------------------------------------------------------------
#define BATCH   8192
#define IN_DIM  4096
#define OUT_DIM 2048
#define DEPTH   9
#define RSTEPS  27
#define WIN     55
#define CENTER  27

// GEMM tiling: 128x64 CTA tile, BK=64, 2-stage ring, 2 CTAs/SM
#define BM 128
#define BN 64
#define BK 64
#define NKT (IN_DIM / BK)            // 64
#define STAGES 2
// Stage layout (128B rows): Ahi 16K | Alo 16K | Bhi 8K | Blo 8K
#define AHI 0
#define ALO 16384
#define BHI 32768
#define BLO 40960
#define STAGE_BYTES 49152
#define SMEM_TOTAL (STAGES * STAGE_BYTES)   // 98304/CTA -> 2 CTAs = 192KB/SM

// ---------------------------------------------------------------------------
// Device-global scratch (static: no runtime allocation)
// ---------------------------------------------------------------------------
__device__ float         g_pb[OUT_DIM];
__device__ __nv_bfloat16 g_xhi[(size_t)BATCH * IN_DIM];
__device__ __nv_bfloat16 g_xlo[(size_t)BATCH * IN_DIM];
__device__ __nv_bfloat16 g_wThi[(size_t)OUT_DIM * IN_DIM];   // W^T [N][K]
__device__ __nv_bfloat16 g_wTlo[(size_t)OUT_DIM * IN_DIM];

// ---------------------------------------------------------------------------
// PTX helpers (base sm_103 ISA only: cp.async / ldmatrix / mma.sync)
// ---------------------------------------------------------------------------
__device__ __forceinline__ uint32_t smem_u32(const void* p) {
    uint32_t a;
    asm("{ .reg .u64 t; cvta.to.shared.u64 t, %1; cvt.u32.u64 %0, t; }"
        : "=r"(a) : "l"(p));
    return a;
}
__device__ __forceinline__ void cpasync16(uint32_t dst, const void* src) {
    asm volatile("cp.async.cg.shared.global [%0], [%1], 16;"
                 :: "r"(dst), "l"(src));
}
#define CP_COMMIT() asm volatile("cp.async.commit_group;" ::: "memory")
#define CP_WAIT0()  asm volatile("cp.async.wait_group 0;"  ::: "memory")

#define LDSM_X4(d, a) \
    asm volatile("ldmatrix.sync.aligned.m8n8.x4.shared.b16 {%0,%1,%2,%3}, [%4];" \
        : "=r"((d)[0]), "=r"((d)[1]), "=r"((d)[2]), "=r"((d)[3]) : "r"(a))

#define MMA16816(c, a, b) \
    asm volatile("mma.sync.aligned.m16n8k16.row.col.f32.bf16.bf16.f32 " \
        "{%0,%1,%2,%3}, {%4,%5,%6,%7}, {%8,%9}, {%0,%1,%2,%3};" \
        : "+f"((c)[0]), "+f"((c)[1]), "+f"((c)[2]), "+f"((c)[3]) \
        : "r"((a)[0]), "r"((a)[1]), "r"((a)[2]), "r"((a)[3]), \
          "r"((b)[0]), "r"((b)[1]))

// SW128 swizzle for 128B physical rows: row r, 16B-chunk cc in 0..7.
// 8 consecutive rows at fixed cc hit 8 distinct chunks (conflict-free).
__device__ __forceinline__ uint32_t swz128(uint32_t base, int row, int cc) {
    return base + row * 128 + (((cc) ^ (row & 7)) << 4);
}

// ---------------------------------------------------------------------------
// Fused prepass kernel: one launch, roles by blockIdx.x range.
//   [0, 32768)            split x -> (hi, lo) bf16
//   [32768, 40960)        transpose+split W -> wT hi/lo
//   [40960, 40968)        universal probs + bias -> g_pb
// ---------------------------------------------------------------------------
#define SPLITX_BLOCKS 32768   // (8192*4096)/(4*256)
#define SPLITW_BLOCKS 8192    // (2048/32)*(4096/32)
#define PROBS_BLOCKS  8
#define PREP_BLOCKS   (SPLITX_BLOCKS + SPLITW_BLOCKS + PROBS_BLOCKS)

__global__ __launch_bounds__(256)
void prep_kernel(const float* __restrict__ x,
                 const float* __restrict__ W,
                 const float* __restrict__ uw,
                 const float* __restrict__ bias) {
    __shared__ float t[32][33];
    const int b   = blockIdx.x;
    const int tid = threadIdx.x;

    if (b < SPLITX_BLOCKS) {
        // ---- split x ----
        size_t i = ((size_t)b * 256 + tid) * 4;
        float4 v = *(const float4*)(x + i);
        __nv_bfloat16 h0 = __float2bfloat16(v.x);
        __nv_bfloat16 h1 = __float2bfloat16(v.y);
        __nv_bfloat16 h2 = __float2bfloat16(v.z);
        __nv_bfloat16 h3 = __float2bfloat16(v.w);
        __nv_bfloat162* ph = (__nv_bfloat162*)(g_xhi + i);
        __nv_bfloat162* pl = (__nv_bfloat162*)(g_xlo + i);
        ph[0] = __nv_bfloat162(h0, h1);
        ph[1] = __nv_bfloat162(h2, h3);
        pl[0] = __nv_bfloat162(__float2bfloat16(v.x - __bfloat162float(h0)),
                               __float2bfloat16(v.y - __bfloat162float(h1)));
        pl[1] = __nv_bfloat162(__float2bfloat16(v.z - __bfloat162float(h2)),
                               __float2bfloat16(v.w - __bfloat162float(h3)));
    } else if (b < SPLITX_BLOCKS + SPLITW_BLOCKS) {
        // ---- transpose + split W ----
        const int bw = b - SPLITX_BLOCKS;
        const int n0 = (bw & 63) * 32;
        const int k0 = (bw >> 6) * 32;
        const int tx = tid & 31, ty = tid >> 5;   // 32 x 8
#pragma unroll
        for (int i = 0; i < 32; i += 8)
            t[ty + i][tx] = W[(size_t)(k0 + ty + i) * OUT_DIM + n0 + tx];
        __syncthreads();
#pragma unroll
        for (int i = 0; i < 32; i += 8) {
            float v = t[tx][ty + i];
            __nv_bfloat16 h = __float2bfloat16(v);
            size_t o = (size_t)(n0 + ty + i) * IN_DIM + k0 + tx;
            g_wThi[o] = h;
            g_wTlo[o] = __float2bfloat16(v - __bfloat162float(h));
        }
    } else {
        // ---- universal probs (dependency-cone trick) ----
        const int o = (b - SPLITX_BLOCKS - SPLITW_BLOCKS) * 256 + tid;
        if (o >= OUT_DIM) return;
        float w[WIN];
#pragma unroll
        for (int j = 0; j < WIN; j++) w[j] = 0.015625f;   // 1/sqrt(4096)
#pragma unroll
        for (int s = 0; s < RSTEPS; s++) {
            const int d = s / 3, g = s % 3;
            float ang = uw[(size_t)d * IN_DIM * OUT_DIM + (size_t)o * OUT_DIM + g];
            float sn, cs;
            sincosf(ang, &sn, &cs);
            float nw[WIN];
            nw[0] = w[0]; nw[WIN - 1] = w[WIN - 1];
#pragma unroll
            for (int j = 1; j < WIN - 1; j++)
                nw[j] = cs * w[j] - sn * w[j + 1] + sn * w[j - 1];
#pragma unroll
            for (int j = 0; j < WIN; j++) w[j] = nw[j];
        }
        g_pb[o] = w[CENTER] * w[CENTER] + bias[o];
    }
}

// ---------------------------------------------------------------------------
// GEMM kernel: C = tanh(x @ W + g_pb) via bf16x3 mma.sync.
// 128x64x64 chunks, 2-stage ring, 2 CTAs/SM, 8 warps, warp tile 32x32.
// Epoch discipline: ONE wait0+__syncthreads per BK=64 chunk (64 epochs vs
// R9's 128). No s_nxt reads: each iteration reads ONLY s_cur; the refill
// (chunk kt+1 -> other stage) is issued mid-iteration at ~25% of the chunk,
// giving ~2300 cyc of latency headroom before the next top-of-loop wait0.
// Within the chunk, 4 ks-phases chain the hi-fragment double buffer.
// ---------------------------------------------------------------------------
__global__ __launch_bounds__(256, 2)
void gemm_bf16x3_kernel(float* __restrict__ out) {
    extern __shared__ char smem[];
    const uint32_t sb = smem_u32(smem);

    const int tid  = threadIdx.x;
    const int lane = tid & 31;
    const int wid  = tid >> 5;
    const int wm   = wid >> 1;          // 0..3  -> m offset wm*32
    const int wn   = wid & 1;           // 0..1  -> n offset wn*32
    const int gid  = lane >> 2;
    const int tg   = lane & 3;
    const int bm   = blockIdx.y * BM;
    const int bn   = blockIdx.x * BN;

    // --- global load mapping: 12 x 16B chunks per thread per BK=64 chunk ---
    // A tiles: 128 rows x 8 cc; thread handles rows r0+32i (i=0..3), cc fixed.
    // B tiles:  64 rows x 8 cc; rows r0+32i (i=0..1).
    const int r0 = tid >> 3;            // 0..31
    const int cA = tid & 7;             // 16B chunk in 128B row

    const __nv_bfloat16* pAh = g_xhi  + (size_t)(bm + r0) * IN_DIM + cA * 8;
    const __nv_bfloat16* pAl = g_xlo  + (size_t)(bm + r0) * IN_DIM + cA * 8;
    const __nv_bfloat16* pBh = g_wThi + (size_t)(bn + r0) * IN_DIM + cA * 8;
    const __nv_bfloat16* pBl = g_wTlo + (size_t)(bn + r0) * IN_DIM + cA * 8;

    // Swizzled dests: row r0+32i keeps (row&7) = r0&7 -> dest = base + i*4096
    const uint32_t dAh = swz128(AHI, r0, cA);
    const uint32_t dAl = swz128(ALO, r0, cA);
    const uint32_t dBh = swz128(BHI, r0, cA);
    const uint32_t dBl = swz128(BLO, r0, cA);

#define ISSUE_CHUNK(stg, kc)                                                 \
    do {                                                                     \
        uint32_t s_ = sb + (stg) * STAGE_BYTES;                              \
        size_t ko_ = (size_t)(kc) * BK;                                      \
        _Pragma("unroll")                                                    \
        for (int i = 0; i < 4; i++) {                                        \
            cpasync16(s_ + dAh + i * 4096, pAh + ko_ + i * 32 * IN_DIM);     \
            cpasync16(s_ + dAl + i * 4096, pAl + ko_ + i * 32 * IN_DIM);     \
        }                                                                    \
        _Pragma("unroll")                                                    \
        for (int i = 0; i < 2; i++) {                                        \
            cpasync16(s_ + dBh + i * 4096, pBh + ko_ + i * 32 * IN_DIM);     \
            cpasync16(s_ + dBl + i * 4096, pBl + ko_ + i * 32 * IN_DIM);     \
        }                                                                    \
    } while (0)

    float acc[2][4][4];
#pragma unroll
    for (int i = 0; i < 2; i++)
#pragma unroll
        for (int j = 0; j < 4; j++)
#pragma unroll
            for (int q = 0; q < 4; q++) acc[i][j][q] = 0.0f;

    // Per-lane ldmatrix logical coordinates (ks phase 0..3 -> cc = ks*2 + ch)
    const int a_rl = lane & 15;               // A: rows m0..m0+15
    const int a_ch = lane >> 4;               // A: +0 / +1 chunk
    const int b4_row = ((lane >> 4) << 3) + (lane & 7);   // B x4 ni-pair
    const int b4_c   = (lane >> 3) & 1;

    uint32_t oA[4][2], oB[4][2];              // [ks][mi] / [ks][nj]
#pragma unroll
    for (int ks = 0; ks < 4; ks++) {
#pragma unroll
        for (int mi = 0; mi < 2; mi++)
            oA[ks][mi] = swz128(0, wm * 32 + mi * 16 + a_rl, ks * 2 + a_ch);
#pragma unroll
        for (int nj = 0; nj < 2; nj++)
            oB[ks][nj] = swz128(0, wn * 32 + nj * 16 + b4_row, ks * 2 + b4_c);
    }

    // Fragment registers: hi double-buffered, lo just-in-time
    uint32_t ah0[2][4], ah1[2][4];
    uint32_t bh0[4][2], bh1[4][2];
    uint32_t al[2][4],  bl[4][2];

#define LOAD_HI(AH, BH, SBASE, KS)                                           \
    do {                                                                     \
        LDSM_X4(AH[0],     (SBASE) + AHI + oA[KS][0]);                       \
        LDSM_X4(AH[1],     (SBASE) + AHI + oA[KS][1]);                       \
        LDSM_X4(&BH[0][0], (SBASE) + BHI + oB[KS][0]);                       \
        LDSM_X4(&BH[2][0], (SBASE) + BHI + oB[KS][1]);                       \
    } while (0)

#define LOAD_LO(SBASE, KS)                                                   \
    do {                                                                     \
        LDSM_X4(al[0],     (SBASE) + ALO + oA[KS][0]);                       \
        LDSM_X4(al[1],     (SBASE) + ALO + oA[KS][1]);                       \
        LDSM_X4(&bl[0][0], (SBASE) + BLO + oB[KS][0]);                       \
        LDSM_X4(&bl[2][0], (SBASE) + BLO + oB[KS][1]);                       \
    } while (0)

    // hh first (hi preloaded a phase ago), then hl / lh (lo just loaded,
    // its LDSM latency covered by the 8 hh MMAs).
#define MMA_PHASE(AH, BH)                                                    \
    do {                                                                     \
        _Pragma("unroll")                                                    \
        for (int mi = 0; mi < 2; mi++)                                       \
            _Pragma("unroll")                                                \
            for (int ni = 0; ni < 4; ni++)                                   \
                MMA16816(acc[mi][ni], AH[mi], BH[ni]);                       \
        _Pragma("unroll")                                                    \
        for (int mi = 0; mi < 2; mi++)                                       \
            _Pragma("unroll")                                                \
            for (int ni = 0; ni < 4; ni++)                                   \
                MMA16816(acc[mi][ni], AH[mi], bl[ni]);                       \
        _Pragma("unroll")                                                    \
        for (int mi = 0; mi < 2; mi++)                                       \
            _Pragma("unroll")                                                \
            for (int ni = 0; ni < 4; ni++)                                   \
                MMA16816(acc[mi][ni], al[mi], BH[ni]);                       \
    } while (0)

    // Prologue: chunk 0 -> stage 0
    ISSUE_CHUNK(0, 0);
    CP_COMMIT();

#pragma unroll 1
    for (int kt = 0; kt < NKT; kt++) {
        // wait0 -> chunk kt (committed >= 3/4 of a chunk ago) complete;
        // barrier -> cross-thread visibility AND protects the refill below
        // (other stage was fully consumed during iter kt-1).
        CP_WAIT0();
        __syncthreads();

        const uint32_t s_cur = sb + (kt & 1) * STAGE_BYTES;

        // phase 0 hi (only exposed LDSM of the chunk; other CTA covers)
        LOAD_HI(ah0, bh0, s_cur, 0);

        // ---- phase 0 ----
        LOAD_LO(s_cur, 0);
        LOAD_HI(ah1, bh1, s_cur, 1);
        MMA_PHASE(ah0, bh0);

        // Refill: chunk kt+1 -> other stage (safe: consumed at kt-1, top
        // barrier passed; no reads of that stage this iteration).
        if (kt + 1 < NKT) {
            ISSUE_CHUNK((kt + 1) & 1, kt + 1);
            CP_COMMIT();
        }

        // ---- phase 1 ----
        LOAD_LO(s_cur, 1);
        LOAD_HI(ah0, bh0, s_cur, 2);
        MMA_PHASE(ah1, bh1);

        // ---- phase 2 ----
        LOAD_LO(s_cur, 2);
        LOAD_HI(ah1, bh1, s_cur, 3);
        MMA_PHASE(ah0, bh0);

        // ---- phase 3 ----
        LOAD_LO(s_cur, 3);
        MMA_PHASE(ah1, bh1);
    }

    // ------------------- epilogue: +pb, tanh, store -------------------
    float pbv[4][2];
#pragma unroll
    for (int ni = 0; ni < 4; ni++) {
        const int col = bn + wn * 32 + ni * 8 + tg * 2;
        pbv[ni][0] = g_pb[col];
        pbv[ni][1] = g_pb[col + 1];
    }
#pragma unroll
    for (int mi = 0; mi < 2; mi++) {
        const int r = bm + wm * 32 + mi * 16 + gid;
#pragma unroll
        for (int ni = 0; ni < 4; ni++) {
            const int col = bn + wn * 32 + ni * 8 + tg * 2;
            float2 v0, v1;
            v0.x = tanhf(acc[mi][ni][0] + pbv[ni][0]);
            v0.y = tanhf(acc[mi][ni][1] + pbv[ni][1]);
            v1.x = tanhf(acc[mi][ni][2] + pbv[ni][0]);
            v1.y = tanhf(acc[mi][ni][3] + pbv[ni][1]);
            *(float2*)(out + (size_t)r * OUT_DIM + col)       = v0;
            *(float2*)(out + (size_t)(r + 8) * OUT_DIM + col) = v1;
        }
    }
}

// ---------------------------------------------------------------------------
// Host launch
// ---------------------------------------------------------------------------
extern "C" void kernel_launch(void* const* d_in, const int* in_sizes, int n_in,
                              void* d_out, int out_size) {
    const float *x = nullptr, *uw = nullptr, *cw = nullptr, *cb = nullptr;
    for (int i = 0; i < n_in; i++) {
        switch (in_sizes[i]) {
            case BATCH * IN_DIM:           x  = (const float*)d_in[i]; break;
            case DEPTH * IN_DIM * OUT_DIM: uw = (const float*)d_in[i]; break;
            case IN_DIM * OUT_DIM:         cw = (const float*)d_in[i]; break;
            case OUT_DIM:                  cb = (const float*)d_in[i]; break;
            default: break;
        }
    }
    float* out = (float*)d_out;

    prep_kernel<<<PREP_BLOCKS, 256>>>(x, cw, uw, cb);

    static int attr_done = 0;
    if (!attr_done) {
        cudaFuncSetAttribute(gemm_bf16x3_kernel,
                             cudaFuncAttributeMaxDynamicSharedMemorySize,
                             SMEM_TOTAL);
        attr_done = 1;
    }
    dim3 grid(OUT_DIM / BN, BATCH / BM);   // (32, 64)
    gemm_bf16x3_kernel<<<grid, 256, SMEM_TOTAL>>>(out);
}